// round 13
// baseline (speedup 1.0000x reference)
#include <cuda_runtime.h>
#include <cstdint>

// ---------------------------------------------------------------------------
// Fast path: S=4096, D=64, L=12.
// 8 threads per q-row (lane = 8*r + c); thread c owns float4 columns
// {c, c+8} of its row -> every Q load / ctx store covers whole 128B lines.
// 512-thread blocks (64 rows) keep the per-block K/V smem gather amortized
// (grid=2048) while __launch_bounds__(512,3) targets 48 warps/SM.
// All global loads issued before the single barrier.
// ---------------------------------------------------------------------------
__global__ __launch_bounds__(512, 3)
void logtrans_fast(const float4* __restrict__ Q4,
                   const float4* __restrict__ K4,
                   const float4* __restrict__ V4,
                   const int* __restrict__ M,
                   float4* __restrict__ C4,
                   float* __restrict__ A)
{
    constexpr int S = 4096;
    constexpr int L = 12;

    __shared__ float4 ks[L][16];
    __shared__ float4 vs[L][16];

    const int tid = threadIdx.x;
    const int c   = tid & 7;            // column-group within the row (0..7)
    const int bh  = blockIdx.y;
    const int q0  = blockIdx.x * 64;    // 512 threads -> 64 rows per block

    const int IND[L] = {0, 2048, 3072, 3584, 3840, 3968, 4032, 4064,
                        4080, 4088, 4092, 4094};

    // ---- issue all global loads up front ----
    const long long qg = (long long)bh * S + q0 + (tid >> 3);
    const float4* Qb = Q4 + qg * 16;

    float4 qa = Qb[c];          // columns 4c..4c+3
    float4 qb = Qb[c + 8];      // columns 32+4c..32+4c+3

    const int* mrow = M + qg * (long long)S;
    unsigned mw = (mrow[IND[c]] ? 1u : 0u) << c;
    if (c < 4)
        mw |= (mrow[IND[c + 4 + 4]] ? 1u : 0u) << (c + 8);  // j = 8..11

    // ---- K/V gathered tiles (12 x 64 floats each), warps 0-5 only ----
    if (tid < L * 16) {
        int j = tid >> 4, cc = tid & 15;
        long long r = (long long)bh * S + IND[j];
        ks[j][cc] = __ldg(&K4[r * 16 + cc]);
        vs[j][cc] = __ldg(&V4[r * 16 + cc]);
    }
    __syncthreads();

    // ---- partial scores over this thread's 8 Q floats ----
    float sc[L];
#pragma unroll
    for (int j = 0; j < L; ++j) {
        float4 ka = ks[j][c];
        float4 kb = ks[j][c + 8];
        float s = qa.x * ka.x;
        s = fmaf(qa.y, ka.y, s);
        s = fmaf(qa.z, ka.z, s);
        s = fmaf(qa.w, ka.w, s);
        s = fmaf(qb.x, kb.x, s);
        s = fmaf(qb.y, kb.y, s);
        s = fmaf(qb.z, kb.z, s);
        s = fmaf(qb.w, kb.w, s);
        sc[j] = s;
    }

    // reduce across the 8 lanes of this row
#pragma unroll
    for (int j = 0; j < L; ++j) {
        sc[j] += __shfl_xor_sync(0xffffffffu, sc[j], 1);
        sc[j] += __shfl_xor_sync(0xffffffffu, sc[j], 2);
        sc[j] += __shfl_xor_sync(0xffffffffu, sc[j], 4);
    }
    mw |= __shfl_xor_sync(0xffffffffu, mw, 1);
    mw |= __shfl_xor_sync(0xffffffffu, mw, 2);
    mw |= __shfl_xor_sync(0xffffffffu, mw, 4);

    // ---- mask + softmax (redundant in the 8 lanes, cheap) ----
#pragma unroll
    for (int j = 0; j < L; ++j)
        sc[j] = ((mw >> j) & 1u) ? -1e9f : sc[j] * 0.125f;   // / sqrt(64)

    float m = sc[0];
#pragma unroll
    for (int j = 1; j < L; ++j) m = fmaxf(m, sc[j]);
    float sum = 0.f;
#pragma unroll
    for (int j = 0; j < L; ++j) {
        float e = __expf(sc[j] - m);
        sc[j] = e;
        sum += e;
    }
    float inv = 1.0f / sum;
#pragma unroll
    for (int j = 0; j < L; ++j) sc[j] *= inv;

    // ---- attn output: lanes 0..2 of each 8-group write 16B each ----
    if (c < 3) {
        float4 o = make_float4(sc[c * 4], sc[c * 4 + 1],
                               sc[c * 4 + 2], sc[c * 4 + 3]);
        reinterpret_cast<float4*>(A + qg * 12)[c] = o;
    }

    // ---- context = attn @ V_g : this thread's 8 output floats ----
    float4 oa = make_float4(0.f, 0.f, 0.f, 0.f);
    float4 ob = make_float4(0.f, 0.f, 0.f, 0.f);
#pragma unroll
    for (int j = 0; j < L; ++j) {
        float a = sc[j];
        float4 va = vs[j][c];
        float4 vb = vs[j][c + 8];
        oa.x = fmaf(a, va.x, oa.x);
        oa.y = fmaf(a, va.y, oa.y);
        oa.z = fmaf(a, va.z, oa.z);
        oa.w = fmaf(a, va.w, oa.w);
        ob.x = fmaf(a, vb.x, ob.x);
        ob.y = fmaf(a, vb.y, ob.y);
        ob.z = fmaf(a, vb.z, ob.z);
        ob.w = fmaf(a, vb.w, ob.w);
    }
    float4* Cb = C4 + qg * 16;
    Cb[c]     = oa;
    Cb[c + 8] = ob;
}

// ---------------------------------------------------------------------------
// Generic fallback (any power-of-two S, D=64)
// ---------------------------------------------------------------------------
__global__ void logtrans_generic(const float* __restrict__ Q,
                                 const float* __restrict__ K,
                                 const float* __restrict__ V,
                                 const int* __restrict__ M,
                                 float* __restrict__ C,
                                 float* __restrict__ A,
                                 int S, int L, long long BHS)
{
    long long qg = (long long)blockIdx.x * blockDim.x + threadIdx.x;
    if (qg >= BHS) return;
    int bh = (int)(qg / S);
    const float* qr = Q + qg * 64;

    float sc[24];
    float m = -3.4e38f;
    for (int j = 0; j < L; ++j) {
        int ind = S - (S >> j);
        const float* kr = K + ((long long)bh * S + ind) * 64;
        float d = 0.f;
        for (int t = 0; t < 64; ++t) d += qr[t] * kr[t];
        d *= 0.125f;
        if (M[qg * (long long)S + ind]) d = -1e9f;
        sc[j] = d;
        m = fmaxf(m, d);
    }
    float sum = 0.f;
    for (int j = 0; j < L; ++j) { sc[j] = __expf(sc[j] - m); sum += sc[j]; }
    float inv = 1.0f / sum;

    float cacc[64];
    for (int t = 0; t < 64; ++t) cacc[t] = 0.f;
    for (int j = 0; j < L; ++j) {
        float a = sc[j] * inv;
        A[qg * L + j] = a;
        int ind = S - (S >> j);
        const float* vr = V + ((long long)bh * S + ind) * 64;
        for (int t = 0; t < 64; ++t) cacc[t] += a * vr[t];
    }
    for (int t = 0; t < 64; ++t) C[qg * 64 + t] = cacc[t];
}

// ---------------------------------------------------------------------------
extern "C" void kernel_launch(void* const* d_in, const int* in_sizes, int n_in,
                              void* d_out, int out_size)
{
    const float* Q = (const float*)d_in[0];
    const float* K = (const float*)d_in[1];
    const float* V = (const float*)d_in[2];
    const int*   M = (const int*)d_in[3];

    long long nq = (long long)in_sizes[0];      // B*H*S*64 (context elements)
    long long nm = (long long)in_sizes[3];      // B*H*S*S
    int S  = (int)((nm / nq) * 64);
    int BH = (int)(nq / ((long long)S * 64));

    int L = 0;
    while ((2 << L) <= S) ++L;                  // L = log2(S)
    if (L > 24) L = 24;

    long long nA = (long long)BH * S * L;
    float* C = (float*)d_out;
    float* A = C + ((long long)out_size - nA);  // attn sits at end of d_out

    if (S == 4096) {
        dim3 grid(S / 64, BH);                  // 64 rows per 512-thread block
        logtrans_fast<<<grid, 512>>>((const float4*)Q, (const float4*)K,
                                     (const float4*)V, M, (float4*)C, A);
    } else {
        long long BHS = (long long)BH * S;
        unsigned blocks = (unsigned)((BHS + 127) / 128);
        logtrans_generic<<<blocks, 128>>>(Q, K, V, M, C, A, S, L, BHS);
    }
}

// round 14
// speedup vs baseline: 1.0334x; 1.0334x over previous
#include <cuda_runtime.h>
#include <cstdint>

// ---------------------------------------------------------------------------
// Fast path: S=4096, D=64, L=12.
// 8 threads per q-row (lane = 8*r + c); thread c owns float4 columns
// {c, c+8} of its row -> every Q load / ctx store covers whole 128B lines.
// 512-thread blocks (64 rows) keep the per-block K/V smem gather amortized
// (grid=2048) while __launch_bounds__(512,3) targets 48 warps/SM.
// All global loads issued before the single barrier.
// ---------------------------------------------------------------------------
__global__ __launch_bounds__(512, 3)
void logtrans_fast(const float4* __restrict__ Q4,
                   const float4* __restrict__ K4,
                   const float4* __restrict__ V4,
                   const int* __restrict__ M,
                   float4* __restrict__ C4,
                   float* __restrict__ A)
{
    constexpr int S = 4096;
    constexpr int L = 12;

    __shared__ float4 ks[L][16];
    __shared__ float4 vs[L][16];

    const int tid = threadIdx.x;
    const int c   = tid & 7;            // column-group within the row (0..7)
    const int bh  = blockIdx.y;
    const int q0  = blockIdx.x * 64;    // 512 threads -> 64 rows per block

    const int IND[L] = {0, 2048, 3072, 3584, 3840, 3968, 4032, 4064,
                        4080, 4088, 4092, 4094};

    // ---- issue all global loads up front ----
    const long long qg = (long long)bh * S + q0 + (tid >> 3);
    const float4* Qb = Q4 + qg * 16;

    float4 qa = Qb[c];          // columns 4c..4c+3
    float4 qb = Qb[c + 8];      // columns 32+4c..32+4c+3

    const int* mrow = M + qg * (long long)S;
    unsigned mw = (mrow[IND[c]] ? 1u : 0u) << c;
    if (c < 4)
        mw |= (mrow[IND[c + 4 + 4]] ? 1u : 0u) << (c + 8);  // j = 8..11

    // ---- K/V gathered tiles (12 x 64 floats each), warps 0-5 only ----
    if (tid < L * 16) {
        int j = tid >> 4, cc = tid & 15;
        long long r = (long long)bh * S + IND[j];
        ks[j][cc] = __ldg(&K4[r * 16 + cc]);
        vs[j][cc] = __ldg(&V4[r * 16 + cc]);
    }
    __syncthreads();

    // ---- partial scores over this thread's 8 Q floats ----
    float sc[L];
#pragma unroll
    for (int j = 0; j < L; ++j) {
        float4 ka = ks[j][c];
        float4 kb = ks[j][c + 8];
        float s = qa.x * ka.x;
        s = fmaf(qa.y, ka.y, s);
        s = fmaf(qa.z, ka.z, s);
        s = fmaf(qa.w, ka.w, s);
        s = fmaf(qb.x, kb.x, s);
        s = fmaf(qb.y, kb.y, s);
        s = fmaf(qb.z, kb.z, s);
        s = fmaf(qb.w, kb.w, s);
        sc[j] = s;
    }

    // reduce across the 8 lanes of this row
#pragma unroll
    for (int j = 0; j < L; ++j) {
        sc[j] += __shfl_xor_sync(0xffffffffu, sc[j], 1);
        sc[j] += __shfl_xor_sync(0xffffffffu, sc[j], 2);
        sc[j] += __shfl_xor_sync(0xffffffffu, sc[j], 4);
    }
    mw |= __shfl_xor_sync(0xffffffffu, mw, 1);
    mw |= __shfl_xor_sync(0xffffffffu, mw, 2);
    mw |= __shfl_xor_sync(0xffffffffu, mw, 4);

    // ---- mask + softmax (redundant in the 8 lanes, cheap) ----
#pragma unroll
    for (int j = 0; j < L; ++j)
        sc[j] = ((mw >> j) & 1u) ? -1e9f : sc[j] * 0.125f;   // / sqrt(64)

    float m = sc[0];
#pragma unroll
    for (int j = 1; j < L; ++j) m = fmaxf(m, sc[j]);
    float sum = 0.f;
#pragma unroll
    for (int j = 0; j < L; ++j) {
        float e = __expf(sc[j] - m);
        sc[j] = e;
        sum += e;
    }
    float inv = 1.0f / sum;
#pragma unroll
    for (int j = 0; j < L; ++j) sc[j] *= inv;

    // ---- attn output: lanes 0..2 of each 8-group write 16B each ----
    if (c < 3) {
        float4 o = make_float4(sc[c * 4], sc[c * 4 + 1],
                               sc[c * 4 + 2], sc[c * 4 + 3]);
        reinterpret_cast<float4*>(A + qg * 12)[c] = o;
    }

    // ---- context = attn @ V_g : this thread's 8 output floats ----
    float4 oa = make_float4(0.f, 0.f, 0.f, 0.f);
    float4 ob = make_float4(0.f, 0.f, 0.f, 0.f);
#pragma unroll
    for (int j = 0; j < L; ++j) {
        float a = sc[j];
        float4 va = vs[j][c];
        float4 vb = vs[j][c + 8];
        oa.x = fmaf(a, va.x, oa.x);
        oa.y = fmaf(a, va.y, oa.y);
        oa.z = fmaf(a, va.z, oa.z);
        oa.w = fmaf(a, va.w, oa.w);
        ob.x = fmaf(a, vb.x, ob.x);
        ob.y = fmaf(a, vb.y, ob.y);
        ob.z = fmaf(a, vb.z, ob.z);
        ob.w = fmaf(a, vb.w, ob.w);
    }
    float4* Cb = C4 + qg * 16;
    Cb[c]     = oa;
    Cb[c + 8] = ob;
}

// ---------------------------------------------------------------------------
// Generic fallback (any power-of-two S, D=64)
// ---------------------------------------------------------------------------
__global__ void logtrans_generic(const float* __restrict__ Q,
                                 const float* __restrict__ K,
                                 const float* __restrict__ V,
                                 const int* __restrict__ M,
                                 float* __restrict__ C,
                                 float* __restrict__ A,
                                 int S, int L, long long BHS)
{
    long long qg = (long long)blockIdx.x * blockDim.x + threadIdx.x;
    if (qg >= BHS) return;
    int bh = (int)(qg / S);
    const float* qr = Q + qg * 64;

    float sc[24];
    float m = -3.4e38f;
    for (int j = 0; j < L; ++j) {
        int ind = S - (S >> j);
        const float* kr = K + ((long long)bh * S + ind) * 64;
        float d = 0.f;
        for (int t = 0; t < 64; ++t) d += qr[t] * kr[t];
        d *= 0.125f;
        if (M[qg * (long long)S + ind]) d = -1e9f;
        sc[j] = d;
        m = fmaxf(m, d);
    }
    float sum = 0.f;
    for (int j = 0; j < L; ++j) { sc[j] = __expf(sc[j] - m); sum += sc[j]; }
    float inv = 1.0f / sum;

    float cacc[64];
    for (int t = 0; t < 64; ++t) cacc[t] = 0.f;
    for (int j = 0; j < L; ++j) {
        float a = sc[j] * inv;
        A[qg * L + j] = a;
        int ind = S - (S >> j);
        const float* vr = V + ((long long)bh * S + ind) * 64;
        for (int t = 0; t < 64; ++t) cacc[t] += a * vr[t];
    }
    for (int t = 0; t < 64; ++t) C[qg * 64 + t] = cacc[t];
}

// ---------------------------------------------------------------------------
extern "C" void kernel_launch(void* const* d_in, const int* in_sizes, int n_in,
                              void* d_out, int out_size)
{
    const float* Q = (const float*)d_in[0];
    const float* K = (const float*)d_in[1];
    const float* V = (const float*)d_in[2];
    const int*   M = (const int*)d_in[3];

    long long nq = (long long)in_sizes[0];      // B*H*S*64 (context elements)
    long long nm = (long long)in_sizes[3];      // B*H*S*S
    int S  = (int)((nm / nq) * 64);
    int BH = (int)(nq / ((long long)S * 64));

    int L = 0;
    while ((2 << L) <= S) ++L;                  // L = log2(S)
    if (L > 24) L = 24;

    long long nA = (long long)BH * S * L;
    float* C = (float*)d_out;
    float* A = C + ((long long)out_size - nA);  // attn sits at end of d_out

    if (S == 4096) {
        dim3 grid(S / 64, BH);                  // 64 rows per 512-thread block
        logtrans_fast<<<grid, 512>>>((const float4*)Q, (const float4*)K,
                                     (const float4*)V, M, (float4*)C, A);
    } else {
        long long BHS = (long long)BH * S;
        unsigned blocks = (unsigned)((BHS + 127) / 128);
        logtrans_generic<<<blocks, 128>>>(Q, K, V, M, C, A, S, L, BHS);
    }
}